// round 1
// baseline (speedup 1.0000x reference)
#include <cuda_runtime.h>
#include <cuda_bf16.h>
#include <math.h>

// Problem constants (shapes fixed by the dataset)
#define MAXN 50000
#define MAXE 600000
#define HDIM 128

// ---------------- device scratch (no allocations allowed) ----------------
__device__ float g_deg[MAXN];
__device__ float g_dis[MAXN];
__device__ float g_hw [MAXN * HDIM];
__device__ float g_bufA[MAXN * HDIM];
__device__ float g_bufB[MAXN * HDIM];
__device__ float g_pool[3 * HDIM];

// ---------------- setup: deg = 1 (self loop), pool = 0 ----------------
__global__ void k_setup(float* deg, float* pool, int n) {
    int i = blockIdx.x * blockDim.x + threadIdx.x;
    if (i < 3 * HDIM) pool[i] = 0.0f;
    if (i < n) deg[i] = 1.0f;
}

__global__ void k_degcount(const int* __restrict__ tgt, float* __restrict__ deg, int e) {
    int i = blockIdx.x * blockDim.x + threadIdx.x;
    if (i < e) atomicAdd(&deg[tgt[i]], 1.0f);
}

__global__ void k_rsqrt(const float* __restrict__ deg, float* __restrict__ dis, int n) {
    int i = blockIdx.x * blockDim.x + threadIdx.x;
    if (i < n) dis[i] = rsqrtf(deg[i]);
}

// ---------------- fused GEMM: HW = A @ W ; OUT = b + dis^2 * HW ----------------
// Tiles: M=128, N=128 (full), K-steps of 32. 256 threads, each computes 8x8.
#define TM 128
#define TK 32

__global__ __launch_bounds__(256) void k_gemm_fused(
    const float* __restrict__ A, const float* __restrict__ W,
    const float* __restrict__ bias, const float* __restrict__ dis,
    float* __restrict__ HW, float* __restrict__ OUT, int M)
{
    __shared__ float As[TK][TM + 1];   // [k][row], pad -> conflict-free transpose store
    __shared__ float Ws[TK][HDIM];     // [k][col]

    const int tid  = threadIdx.x;
    const int row0 = blockIdx.x * TM;
    const int ty   = tid >> 4;         // 0..15 : row group
    const int tx   = tid & 15;         // 0..15 : col group

    float acc[8][8];
#pragma unroll
    for (int i = 0; i < 8; i++)
#pragma unroll
        for (int j = 0; j < 8; j++) acc[i][j] = 0.0f;

    for (int k0 = 0; k0 < HDIM; k0 += TK) {
        // load A tile: 128 rows x 32 k  (1024 float4, 4 per thread), transpose into As
#pragma unroll
        for (int it = 0; it < 4; it++) {
            int i  = tid + it * 256;           // 0..1023
            int r  = i >> 3;                   // row within tile
            int kq = i & 7;                    // which float4 of 32 k
            float4 v = make_float4(0.f, 0.f, 0.f, 0.f);
            int gr = row0 + r;
            if (gr < M) v = *(const float4*)(A + (size_t)gr * HDIM + k0 + kq * 4);
            As[kq * 4 + 0][r] = v.x;
            As[kq * 4 + 1][r] = v.y;
            As[kq * 4 + 2][r] = v.z;
            As[kq * 4 + 3][r] = v.w;
        }
        // load W tile: 32 k x 128 cols (1024 float4)
#pragma unroll
        for (int it = 0; it < 4; it++) {
            int i  = tid + it * 256;
            int kk = i >> 5;                   // k row (32 float4 per row)
            int cq = i & 31;
            *(float4*)&Ws[kk][cq * 4] = *(const float4*)(W + (size_t)(k0 + kk) * HDIM + cq * 4);
        }
        __syncthreads();

#pragma unroll
        for (int k = 0; k < TK; k++) {
            float a[8], b[8];
#pragma unroll
            for (int i = 0; i < 8; i++) a[i] = As[k][ty * 8 + i];
#pragma unroll
            for (int j = 0; j < 8; j++) b[j] = Ws[k][tx * 8 + j];
#pragma unroll
            for (int i = 0; i < 8; i++)
#pragma unroll
                for (int j = 0; j < 8; j++) acc[i][j] += a[i] * b[j];
        }
        __syncthreads();
    }

    // epilogue: write HW and OUT = bias + dis^2 * HW  (self-loop term pre-added)
#pragma unroll
    for (int i = 0; i < 8; i++) {
        int gr = row0 + ty * 8 + i;
        if (gr >= M) continue;
        float d  = dis[gr];
        float d2 = d * d;
#pragma unroll
        for (int j = 0; j < 8; j += 4) {
            int c = tx * 8 + j;
            float4 hv = make_float4(acc[i][j], acc[i][j+1], acc[i][j+2], acc[i][j+3]);
            *(float4*)(HW + (size_t)gr * HDIM + c) = hv;
            float4 ov;
            ov.x = bias[c + 0] + d2 * hv.x;
            ov.y = bias[c + 1] + d2 * hv.y;
            ov.z = bias[c + 2] + d2 * hv.z;
            ov.w = bias[c + 3] + d2 * hv.w;
            *(float4*)(OUT + (size_t)gr * HDIM + c) = ov;
        }
    }
}

// ---------------- edge scatter: OUT[tgt] += dis[s]*dis[t] * HW[src] ----------------
// One warp per edge; lane handles 4 contiguous floats.
__global__ __launch_bounds__(256) void k_scatter(
    const int* __restrict__ src, const int* __restrict__ tgt,
    const float* __restrict__ dis, const float* __restrict__ HW,
    float* __restrict__ OUT, int E)
{
    int w    = (blockIdx.x * blockDim.x + threadIdx.x) >> 5;
    int lane = threadIdx.x & 31;
    if (w >= E) return;
    int s = src[w];
    int t = tgt[w];
    float nw = dis[s] * dis[t];
    float4 v = *(const float4*)(HW + (size_t)s * HDIM + lane * 4);
    float* o = OUT + (size_t)t * HDIM + lane * 4;
    atomicAdd(o + 0, nw * v.x);
    atomicAdd(o + 1, nw * v.y);
    atomicAdd(o + 2, nw * v.z);
    atomicAdd(o + 3, nw * v.w);
}

// ---------------- relu in place + column-sum pooling ----------------
__global__ __launch_bounds__(128) void k_relu_pool(
    float* __restrict__ X, float* __restrict__ pool, int off, int n)
{
    int c = threadIdx.x;  // 128 columns
    float s = 0.0f;
    for (int r = blockIdx.x; r < n; r += gridDim.x) {
        float v = X[(size_t)r * HDIM + c];
        v = fmaxf(v, 0.0f);
        X[(size_t)r * HDIM + c] = v;
        s += v;
    }
    atomicAdd(pool + off + c, s);
}

// ---------------- tiny MLP head: 384 -> 128 -> 64 -> 10 ----------------
__global__ __launch_bounds__(128) void k_mlp(
    const float* __restrict__ pool,
    const float* __restrict__ fw1, const float* __restrict__ fb1,
    const float* __restrict__ fw2, const float* __restrict__ fb2,
    const float* __restrict__ fw3, const float* __restrict__ fb3,
    float* __restrict__ out)
{
    __shared__ float p[3 * HDIM];
    __shared__ float h1[128];
    __shared__ float h2[64];
    int t = threadIdx.x;

    for (int i = t; i < 3 * HDIM; i += 128) p[i] = pool[i];
    __syncthreads();

    float s = fb1[t];
#pragma unroll 8
    for (int k = 0; k < 3 * HDIM; k++) s += p[k] * fw1[k * 128 + t];
    h1[t] = fmaxf(s, 0.0f);
    __syncthreads();

    if (t < 64) {
        float s2 = fb2[t];
#pragma unroll 8
        for (int k = 0; k < 128; k++) s2 += h1[k] * fw2[k * 64 + t];
        h2[t] = fmaxf(s2, 0.0f);
    }
    __syncthreads();

    if (t < 10) {
        float s3 = fb3[t];
#pragma unroll
        for (int k = 0; k < 64; k++) s3 += h2[k] * fw3[k * 10 + t];
        out[t] = s3;
    }
}

// ---------------- launch ----------------
extern "C" void kernel_launch(void* const* d_in, const int* in_sizes, int n_in,
                              void* d_out, int out_size)
{
    const float* x   = (const float*)d_in[0];
    const int*   ei  = (const int*)  d_in[1];
    const float* W1  = (const float*)d_in[2];
    const float* b1  = (const float*)d_in[3];
    const float* W2  = (const float*)d_in[4];
    const float* b2  = (const float*)d_in[5];
    const float* W3  = (const float*)d_in[6];
    const float* b3  = (const float*)d_in[7];
    const float* fw1 = (const float*)d_in[8];
    const float* fb1 = (const float*)d_in[9];
    const float* fw2 = (const float*)d_in[10];
    const float* fb2 = (const float*)d_in[11];
    const float* fw3 = (const float*)d_in[12];
    const float* fb3 = (const float*)d_in[13];

    const int N = in_sizes[0] / HDIM;
    const int E = in_sizes[1] / 2;
    const int* src = ei;
    const int* tgt = ei + E;

    float *deg, *dis, *hw, *bufA, *bufB, *pool;
    cudaGetSymbolAddress((void**)&deg,  g_deg);
    cudaGetSymbolAddress((void**)&dis,  g_dis);
    cudaGetSymbolAddress((void**)&hw,   g_hw);
    cudaGetSymbolAddress((void**)&bufA, g_bufA);
    cudaGetSymbolAddress((void**)&bufB, g_bufB);
    cudaGetSymbolAddress((void**)&pool, g_pool);

    const int gemm_blocks = (N + TM - 1) / TM;
    const int scat_blocks = (E * 32 + 255) / 256;

    k_setup   <<<(N + 255) / 256, 256>>>(deg, pool, N);
    k_degcount<<<(E + 255) / 256, 256>>>(tgt, deg, E);
    k_rsqrt   <<<(N + 255) / 256, 256>>>(deg, dis, N);

    // layer 1: x -> bufA
    k_gemm_fused<<<gemm_blocks, 256>>>(x, W1, b1, dis, hw, bufA, N);
    k_scatter   <<<scat_blocks, 256>>>(src, tgt, dis, hw, bufA, E);
    k_relu_pool <<<512, 128>>>(bufA, pool, 0, N);

    // layer 2: bufA -> bufB
    k_gemm_fused<<<gemm_blocks, 256>>>(bufA, W2, b2, dis, hw, bufB, N);
    k_scatter   <<<scat_blocks, 256>>>(src, tgt, dis, hw, bufB, E);
    k_relu_pool <<<512, 128>>>(bufB, pool, HDIM, N);

    // layer 3: bufB -> bufA (x1 no longer needed)
    k_gemm_fused<<<gemm_blocks, 256>>>(bufB, W3, b3, dis, hw, bufA, N);
    k_scatter   <<<scat_blocks, 256>>>(src, tgt, dis, hw, bufA, E);
    k_relu_pool <<<512, 128>>>(bufA, pool, 2 * HDIM, N);

    k_mlp<<<1, 128>>>(pool, fw1, fb1, fw2, fb2, fw3, fb3, (float*)d_out);
}

// round 4
// speedup vs baseline: 1.8341x; 1.8341x over previous
#include <cuda_runtime.h>
#include <cuda_bf16.h>
#include <math.h>

// Problem constants (shapes fixed by the dataset)
#define MAXN 50000
#define MAXE 600000
#define HDIM 128

// ---------------- device scratch (no allocations allowed) ----------------
__device__ float g_deg[MAXN];
__device__ float g_dis[MAXN];
__device__ float g_hw [MAXN * HDIM];
__device__ float g_bufA[MAXN * HDIM];
__device__ float g_bufB[MAXN * HDIM];
__device__ float g_pool[3 * HDIM];

// vectorized global reduction (sm_90+)
__device__ __forceinline__ void red_add_v4(float* addr, float a, float b, float c, float d) {
    asm volatile("red.global.add.v4.f32 [%0], {%1, %2, %3, %4};"
                 :: "l"(addr), "f"(a), "f"(b), "f"(c), "f"(d) : "memory");
}

// ---------------- setup: deg = 1 (self loop), pool = 0 ----------------
__global__ void k_setup(float* deg, float* pool, int n) {
    int i = blockIdx.x * blockDim.x + threadIdx.x;
    if (i < 3 * HDIM) pool[i] = 0.0f;
    if (i < n) deg[i] = 1.0f;
}

__global__ void k_degcount(const int* __restrict__ tgt, float* __restrict__ deg, int e) {
    int i = blockIdx.x * blockDim.x + threadIdx.x;
    if (i < e) atomicAdd(&deg[tgt[i]], 1.0f);
}

__global__ void k_rsqrt(const float* __restrict__ deg, float* __restrict__ dis, int n) {
    int i = blockIdx.x * blockDim.x + threadIdx.x;
    if (i < n) dis[i] = rsqrtf(deg[i]);
}

// ---------------- fused GEMM: HW = relu?(A) @ W ; OUT = b + dis^2 * HW ----------------
// Tiles: M=128, N=128 (full), K-steps of 32. 256 threads, each computes 8x8.
#define TM 128
#define TK 32

__global__ __launch_bounds__(256) void k_gemm_fused(
    const float* __restrict__ A, const float* __restrict__ W,
    const float* __restrict__ bias, const float* __restrict__ dis,
    float* __restrict__ HW, float* __restrict__ OUT, int M, int doRelu)
{
    __shared__ float As[TK][TM + 1];   // [k][row], pad -> conflict-free transpose store
    __shared__ float Ws[TK][HDIM];     // [k][col]

    const int tid  = threadIdx.x;
    const int row0 = blockIdx.x * TM;
    const int ty   = tid >> 4;         // 0..15 : row group
    const int tx   = tid & 15;         // 0..15 : col group

    float acc[8][8];
#pragma unroll
    for (int i = 0; i < 8; i++)
#pragma unroll
        for (int j = 0; j < 8; j++) acc[i][j] = 0.0f;

    for (int k0 = 0; k0 < HDIM; k0 += TK) {
        // load A tile: 128 rows x 32 k  (1024 float4, 4 per thread), transpose into As
#pragma unroll
        for (int it = 0; it < 4; it++) {
            int i  = tid + it * 256;           // 0..1023
            int r  = i >> 3;                   // row within tile
            int kq = i & 7;                    // which float4 of 32 k
            float4 v = make_float4(0.f, 0.f, 0.f, 0.f);
            int gr = row0 + r;
            if (gr < M) v = *(const float4*)(A + (size_t)gr * HDIM + k0 + kq * 4);
            if (doRelu) {
                v.x = fmaxf(v.x, 0.f); v.y = fmaxf(v.y, 0.f);
                v.z = fmaxf(v.z, 0.f); v.w = fmaxf(v.w, 0.f);
            }
            As[kq * 4 + 0][r] = v.x;
            As[kq * 4 + 1][r] = v.y;
            As[kq * 4 + 2][r] = v.z;
            As[kq * 4 + 3][r] = v.w;
        }
        // load W tile: 32 k x 128 cols (1024 float4)
#pragma unroll
        for (int it = 0; it < 4; it++) {
            int i  = tid + it * 256;
            int kk = i >> 5;                   // k row (32 float4 per row)
            int cq = i & 31;
            *(float4*)&Ws[kk][cq * 4] = *(const float4*)(W + (size_t)(k0 + kk) * HDIM + cq * 4);
        }
        __syncthreads();

#pragma unroll
        for (int k = 0; k < TK; k++) {
            float a[8], b[8];
#pragma unroll
            for (int i = 0; i < 8; i++) a[i] = As[k][ty * 8 + i];
#pragma unroll
            for (int j = 0; j < 8; j++) b[j] = Ws[k][tx * 8 + j];
#pragma unroll
            for (int i = 0; i < 8; i++)
#pragma unroll
                for (int j = 0; j < 8; j++) acc[i][j] += a[i] * b[j];
        }
        __syncthreads();
    }

    // epilogue: write HW and OUT = bias + dis^2 * HW  (self-loop term pre-added)
#pragma unroll
    for (int i = 0; i < 8; i++) {
        int gr = row0 + ty * 8 + i;
        if (gr >= M) continue;
        float d  = dis[gr];
        float d2 = d * d;
#pragma unroll
        for (int j = 0; j < 8; j += 4) {
            int c = tx * 8 + j;
            float4 hv = make_float4(acc[i][j], acc[i][j+1], acc[i][j+2], acc[i][j+3]);
            *(float4*)(HW + (size_t)gr * HDIM + c) = hv;
            float4 ov;
            ov.x = bias[c + 0] + d2 * hv.x;
            ov.y = bias[c + 1] + d2 * hv.y;
            ov.z = bias[c + 2] + d2 * hv.z;
            ov.w = bias[c + 3] + d2 * hv.w;
            *(float4*)(OUT + (size_t)gr * HDIM + c) = ov;
        }
    }
}

// ---------------- edge scatter: OUT[tgt] += dis[s]*dis[t] * HW[src] ----------------
// One warp per edge; lane handles 4 contiguous floats; one v4 RED per lane.
__global__ __launch_bounds__(256) void k_scatter(
    const int* __restrict__ src, const int* __restrict__ tgt,
    const float* __restrict__ dis, const float* __restrict__ HW,
    float* __restrict__ OUT, int E)
{
    int w    = (blockIdx.x * blockDim.x + threadIdx.x) >> 5;
    int lane = threadIdx.x & 31;
    if (w >= E) return;
    int s = __ldg(&src[w]);
    int t = __ldg(&tgt[w]);
    float nw = dis[s] * dis[t];
    float4 v = *(const float4*)(HW + (size_t)s * HDIM + lane * 4);
    float* o = OUT + (size_t)t * HDIM + lane * 4;
    red_add_v4(o, nw * v.x, nw * v.y, nw * v.z, nw * v.w);
}

// ---------------- read-only pool: pool[off+c] += sum_r relu(X[r][c]) ----------------
__global__ __launch_bounds__(256) void k_pool(
    const float* __restrict__ X, float* __restrict__ pool, int off, int n)
{
    int lane = threadIdx.x & 31;   // column group: cols lane*4 .. +3
    int warp = threadIdx.x >> 5;   // 8 warps = 8 rows per block-iter
    float4 acc = make_float4(0.f, 0.f, 0.f, 0.f);
    for (int r = blockIdx.x * 8 + warp; r < n; r += gridDim.x * 8) {
        float4 v = *(const float4*)(X + (size_t)r * HDIM + lane * 4);
        acc.x += fmaxf(v.x, 0.f);
        acc.y += fmaxf(v.y, 0.f);
        acc.z += fmaxf(v.z, 0.f);
        acc.w += fmaxf(v.w, 0.f);
    }
    __shared__ float4 sh[8][32];
    sh[warp][lane] = acc;
    __syncthreads();
    if (warp == 0) {
        float4 a = sh[0][lane];
#pragma unroll
        for (int w2 = 1; w2 < 8; w2++) {
            float4 b = sh[w2][lane];
            a.x += b.x; a.y += b.y; a.z += b.z; a.w += b.w;
        }
        red_add_v4(pool + off + lane * 4, a.x, a.y, a.z, a.w);
    }
}

// ---------------- tiny MLP head: 384 -> 128 -> 64 -> 10 ----------------
__global__ __launch_bounds__(128) void k_mlp(
    const float* __restrict__ pool,
    const float* __restrict__ fw1, const float* __restrict__ fb1,
    const float* __restrict__ fw2, const float* __restrict__ fb2,
    const float* __restrict__ fw3, const float* __restrict__ fb3,
    float* __restrict__ out)
{
    __shared__ float p[3 * HDIM];
    __shared__ float h1[128];
    __shared__ float h2[64];
    int t = threadIdx.x;

    for (int i = t; i < 3 * HDIM; i += 128) p[i] = pool[i];
    __syncthreads();

    float s = fb1[t];
#pragma unroll 8
    for (int k = 0; k < 3 * HDIM; k++) s += p[k] * fw1[k * 128 + t];
    h1[t] = fmaxf(s, 0.0f);
    __syncthreads();

    if (t < 64) {
        float s2 = fb2[t];
#pragma unroll 8
        for (int k = 0; k < 128; k++) s2 += h1[k] * fw2[k * 64 + t];
        h2[t] = fmaxf(s2, 0.0f);
    }
    __syncthreads();

    if (t < 10) {
        float s3 = fb3[t];
#pragma unroll
        for (int k = 0; k < 64; k++) s3 += h2[k] * fw3[k * 10 + t];
        out[t] = s3;
    }
}

// ---------------- launch ----------------
extern "C" void kernel_launch(void* const* d_in, const int* in_sizes, int n_in,
                              void* d_out, int out_size)
{
    const float* x   = (const float*)d_in[0];
    const int*   ei  = (const int*)  d_in[1];
    const float* W1  = (const float*)d_in[2];
    const float* b1  = (const float*)d_in[3];
    const float* W2  = (const float*)d_in[4];
    const float* b2  = (const float*)d_in[5];
    const float* W3  = (const float*)d_in[6];
    const float* b3  = (const float*)d_in[7];
    const float* fw1 = (const float*)d_in[8];
    const float* fb1 = (const float*)d_in[9];
    const float* fw2 = (const float*)d_in[10];
    const float* fb2 = (const float*)d_in[11];
    const float* fw3 = (const float*)d_in[12];
    const float* fb3 = (const float*)d_in[13];

    const int N = in_sizes[0] / HDIM;
    const int E = in_sizes[1] / 2;
    const int* src = ei;
    const int* tgt = ei + E;

    float *deg, *dis, *hw, *bufA, *bufB, *pool;
    cudaGetSymbolAddress((void**)&deg,  g_deg);
    cudaGetSymbolAddress((void**)&dis,  g_dis);
    cudaGetSymbolAddress((void**)&hw,   g_hw);
    cudaGetSymbolAddress((void**)&bufA, g_bufA);
    cudaGetSymbolAddress((void**)&bufB, g_bufB);
    cudaGetSymbolAddress((void**)&pool, g_pool);

    const int gemm_blocks = (N + TM - 1) / TM;
    const int scat_blocks = (E * 32 + 255) / 256;

    k_setup   <<<(N + 255) / 256, 256>>>(deg, pool, N);
    k_degcount<<<(E + 255) / 256, 256>>>(tgt, deg, E);
    k_rsqrt   <<<(N + 255) / 256, 256>>>(deg, dis, N);

    // layer 1: x -> bufA   (x1 = relu(bufA), applied lazily on read)
    k_gemm_fused<<<gemm_blocks, 256>>>(x, W1, b1, dis, hw, bufA, N, 0);
    k_scatter   <<<scat_blocks, 256>>>(src, tgt, dis, hw, bufA, E);
    k_pool      <<<512, 256>>>(bufA, pool, 0, N);

    // layer 2: relu(bufA) -> bufB
    k_gemm_fused<<<gemm_blocks, 256>>>(bufA, W2, b2, dis, hw, bufB, N, 1);
    k_scatter   <<<scat_blocks, 256>>>(src, tgt, dis, hw, bufB, E);
    k_pool      <<<512, 256>>>(bufB, pool, HDIM, N);

    // layer 3: relu(bufB) -> bufA
    k_gemm_fused<<<gemm_blocks, 256>>>(bufB, W3, b3, dis, hw, bufA, N, 1);
    k_scatter   <<<scat_blocks, 256>>>(src, tgt, dis, hw, bufA, E);
    k_pool      <<<512, 256>>>(bufA, pool, 2 * HDIM, N);

    k_mlp<<<1, 128>>>(pool, fw1, fb1, fw2, fb2, fw3, fb3, (float*)d_out);
}